// round 14
// baseline (speedup 1.0000x reference)
#include <cuda_runtime.h>
#include <cfloat>

// xp: (32, 64, 64, 512) fp32, m innermost. out: (32, 48*512), bin = iw*6+ih.
// Resize is identity. Row bins: 8 rows each. Col edges: {0,11,21,32,43,53,64}.
//
// R14: the locked R3 optimum (42.6-43.3us ncu / 78% DRAM across 3 runs =
// chip LTS cap, 98.5% of achieved-BW floor) made fully branchless: every
// block processes 11 column slots; narrow bins (nc=10) clamp slot 10 to
// column 9 -- a duplicate load of a just-read address (L1/L2 hit, zero extra
// DRAM traffic) and max(x,x)=x keeps the result exact. Uniform control flow
// across all 1536 blocks lets ptxas batch one 22-load window and removes
// the bimodal block-duration split. Everything else identical to R3.

#define B_DIM 32
#define W_DIM 64
#define H_DIM 64
#define M_DIM 512
#define W_BINS 8
#define H_BINS 6
#define M4 (M_DIM / 4)            // 128 float4 lanes per (b,r,c)
#define ROW_STRIDE (H_DIM * M4)   // float4 elems per image row

__constant__ int C_EDGE[H_BINS + 1] = {0, 11, 21, 32, 43, 53, 64};

static __device__ __forceinline__ float4 fmax4(float4 a, float4 b) {
    a.x = fmaxf(a.x, b.x);
    a.y = fmaxf(a.y, b.y);
    a.z = fmaxf(a.z, b.z);
    a.w = fmaxf(a.w, b.w);
    return a;
}

static __device__ __forceinline__ float4 ldcs4(const float4* p) {
    return __ldcs(p);
}

// One block per (batch, bin). 128 threads; thread t owns channels [4t, 4t+4).
__global__ __launch_bounds__(M4, 6)
void adaptive_maxpool_kernel(const float4* __restrict__ x4, float4* __restrict__ out4) {
    const int bin = blockIdx.x;       // 0..47  (iw*6 + ih)
    const int b   = blockIdx.y;       // 0..31
    const int iw  = bin / H_BINS;
    const int ih  = bin - iw * H_BINS;

    const int r1 = iw * (W_DIM / W_BINS);          // 8 rows per bin
    const int c1 = C_EDGE[ih];
    const int nc = C_EDGE[ih + 1] - c1;            // 10 or 11
    // Slot 10 offset: column 10 for wide bins, column 9 (duplicate) for
    // narrow bins. max(x, x) = x, and the duplicate hits L1/L2.
    const size_t off10 = (size_t)(nc - 1 >= 10 ? 10 : 9) * M4;

    const int t = threadIdx.x;                     // 0..127
    const float4* base =
        x4 + ((size_t)(b * W_DIM + r1) * H_DIM + c1) * M4 + t;

    float4 acc = make_float4(-FLT_MAX, -FLT_MAX, -FLT_MAX, -FLT_MAX);

    // 8 rows as 4 row-pairs; per pair 2x11 independent loads, branch-free.
    #pragma unroll 1
    for (int rp = 0; rp < 4; ++rp) {
        const float4* r0 = base + (size_t)(2 * rp) * ROW_STRIDE;
        const float4* r1p = r0 + ROW_STRIDE;

        #pragma unroll
        for (int c = 0; c < 10; ++c) {
            float4 va = ldcs4(r0  + (size_t)c * M4);
            float4 vb = ldcs4(r1p + (size_t)c * M4);
            acc = fmax4(acc, fmax4(va, vb));
        }
        {
            float4 va = ldcs4(r0  + off10);
            float4 vb = ldcs4(r1p + off10);
            acc = fmax4(acc, fmax4(va, vb));
        }
    }

    out4[((size_t)b * (W_BINS * H_BINS) + bin) * M4 + t] = acc;
}

extern "C" void kernel_launch(void* const* d_in, const int* in_sizes, int n_in,
                              void* d_out, int out_size) {
    (void)in_sizes; (void)n_in; (void)out_size;
    const float4* x4 = (const float4*)d_in[0];
    float4* o4 = (float4*)d_out;

    dim3 grid(W_BINS * H_BINS, B_DIM);   // (48, 32) = 1536 blocks
    adaptive_maxpool_kernel<<<grid, M4>>>(x4, o4);
}